// round 8
// baseline (speedup 1.0000x reference)
#include <cuda_runtime.h>

// spixel_upsample2d: out[b, 4h+a, 4w+d] = sum_{c<2, ky<3, kx<3}
//     cv[b, c, h+ky-1, w+kx-1] * sp[b, c*9 + ky*3+kx, 4h+a, 4w+d]
// cv: (4,2,128,256) fp32 (1 MB, L2-resident)   sp: (4,18,512,1024) fp32 (151 MB, streamed)
// out: (4,1,512,1024) fp32 (8.4 MB)
//
// R5: persistent 592-CTA launch (148 SMs x occ 4 = exactly one startup wave)
// + dynamic row work-stealing via a global atomic counter. Kills the 3.46-wave
// scheduling quantization that cost ~13% of chip bandwidth in R2-R4.
// Counter self-resets via the classic last-block pattern (graph-replay safe).

#define BB 4
#define CC 2
#define HH 128
#define WW 256
#define H4 512
#define W4 1024
#define NROWS (BB * H4)          // 2048 work units (one output row each)
#define NCTAS 592                // 148 SMs * 4 CTAs/SM

__device__ unsigned g_row_ctr  = 0;
__device__ unsigned g_done_ctr = 0;

__global__ __launch_bounds__(256, 4)
void spixel_up_kernel(const float* __restrict__ cv,
                      const float* __restrict__ sp,
                      float* __restrict__ out) {
    __shared__ unsigned s_row;
    const int w = threadIdx.x;                      // coarse column 0..255
    const size_t ch_stride4 = (size_t)H4 * W4 / 4;  // float4 per sp channel

    for (;;) {
        if (w == 0) s_row = atomicAdd(&g_row_ctr, 1u);
        __syncthreads();
        const unsigned row = s_row;
        __syncthreads();          // everyone read s_row before next overwrite
        if (row >= NROWS) break;

        const int y = row & (H4 - 1);
        const int b = row >> 9;
        const int h = y >> 2;

        // ---- 18 patch values (cv is L2/L1-hot) ----
        float p[CC][9];
#pragma unroll
        for (int c = 0; c < CC; c++) {
            const float* __restrict__ xb = cv + ((size_t)(b * CC + c) * HH) * WW;
#pragma unroll
            for (int ky = 0; ky < 3; ky++) {
                const int hh = h + ky - 1;
                const bool hv = (hh >= 0) && (hh < HH);
#pragma unroll
                for (int kx = 0; kx < 3; kx++) {
                    const int wwc = w + kx - 1;
                    const bool v = hv && (wwc >= 0) && (wwc < WW);
                    p[c][ky * 3 + kx] = v ? __ldg(&xb[(size_t)hh * WW + wwc]) : 0.0f;
                }
            }
        }

        // ---- 18 independent float4 streams from sp, accumulate ----
        const float4* __restrict__ spb =
            reinterpret_cast<const float4*>(sp) +
            (size_t)b * 18 * ch_stride4 + (size_t)y * (W4 / 4) + w;

        float4 acc = make_float4(0.f, 0.f, 0.f, 0.f);
#pragma unroll
        for (int c = 0; c < CC; c++) {
#pragma unroll
            for (int k = 0; k < 9; k++) {
                const float4 s = spb[(size_t)(c * 9 + k) * ch_stride4];
                const float v = p[c][k];
                acc.x = fmaf(v, s.x, acc.x);
                acc.y = fmaf(v, s.y, acc.y);
                acc.z = fmaf(v, s.z, acc.z);
                acc.w = fmaf(v, s.w, acc.w);
            }
        }
        reinterpret_cast<float4*>(out)[(size_t)b * H4 * (W4 / 4) +
                                       (size_t)y * (W4 / 4) + w] = acc;
    }

    // ---- last-block counter reset (deterministic across graph replays) ----
    if (w == 0) {
        __threadfence();
        const unsigned d = atomicAdd(&g_done_ctr, 1u);
        if (d == NCTAS - 1) {
            g_row_ctr  = 0u;
            g_done_ctr = 0u;
            __threadfence();
        }
    }
}

extern "C" void kernel_launch(void* const* d_in, const int* in_sizes, int n_in,
                              void* d_out, int out_size) {
    // Bind inputs by element count (robust to metadata ordering).
    const int CV_N = BB * CC * HH * WW;          // 262144
    const float* cv = nullptr;
    const float* sp = nullptr;
    for (int i = 0; i < n_in; i++) {
        if (in_sizes[i] == CV_N) cv = (const float*)d_in[i];
        else                     sp = (const float*)d_in[i];
    }
    float* out = (float*)d_out;

    spixel_up_kernel<<<NCTAS, 256>>>(cv, sp, out);
}

// round 10
// speedup vs baseline: 1.0391x; 1.0391x over previous
#include <cuda_runtime.h>

// spixel_upsample2d: out[b, 4h+a, 4w+d] = sum_{c<2, ky<3, kx<3}
//     cv[b, c, h+ky-1, w+kx-1] * sp[b, c*9 + ky*3+kx, 4h+a, 4w+d]
// cv: (4,2,128,256) fp32 (1 MB, L2-resident)  sp: (4,18,512,1024) fp32 (151 MB streamed)
// out: (4,1,512,1024) fp32 (8.4 MB)
//
// R8: back to the R2 schedule (2048 CTAs x 256 thr, one output row per CTA --
// the empirical best; R3-R5 scheduling experiments all regressed). One change:
// lift the 64-reg ceiling (launch_bounds occ 4 -> 2, ~128 regs) and stage all
// 18 float4 loads into registers BEFORE the FMA chain, so the full 18-deep
// LDG.128 stream is in flight per thread instead of reg-pressure batches.

#define BB 4
#define CC 2
#define HH 128
#define WW 256
#define H4 512
#define W4 1024

__global__ __launch_bounds__(256, 2)
void spixel_up_kernel(const float* __restrict__ cv,
                      const float* __restrict__ sp,
                      float* __restrict__ out) {
    const int w  = threadIdx.x;            // coarse column 0..255
    const int by = blockIdx.x;             // 0..2047 = b*512 + y
    const int y  = by & (H4 - 1);          // output row
    const int b  = by >> 9;                // batch
    const int h  = y >> 2;                 // coarse row

    const size_t ch_stride4 = (size_t)H4 * W4 / 4;   // float4 per sp channel
    const float4* __restrict__ spb =
        reinterpret_cast<const float4*>(sp) +
        (size_t)b * 18 * ch_stride4 + (size_t)y * (W4 / 4) + w;

    // ---- issue all 18 independent LDG.128 first (no deps, full MLP) ----
    float4 s[18];
#pragma unroll
    for (int j = 0; j < 18; j++)
        s[j] = spb[(size_t)j * ch_stride4];

    // ---- 18 patch values (L1/L2-hot, overlap with sp latency) ----
    float p[18];
#pragma unroll
    for (int c = 0; c < CC; c++) {
        const float* __restrict__ xb = cv + ((size_t)(b * CC + c) * HH) * WW;
#pragma unroll
        for (int ky = 0; ky < 3; ky++) {
            const int hh = h + ky - 1;
            const bool hv = (hh >= 0) && (hh < HH);
#pragma unroll
            for (int kx = 0; kx < 3; kx++) {
                const int wwc = w + kx - 1;
                const bool v = hv && (wwc >= 0) && (wwc < WW);
                p[c * 9 + ky * 3 + kx] = v ? __ldg(&xb[(size_t)hh * WW + wwc]) : 0.0f;
            }
        }
    }

    // ---- FMA chain (consumes loads in issue order) ----
    float4 acc = make_float4(0.f, 0.f, 0.f, 0.f);
#pragma unroll
    for (int j = 0; j < 18; j++) {
        acc.x = fmaf(p[j], s[j].x, acc.x);
        acc.y = fmaf(p[j], s[j].y, acc.y);
        acc.z = fmaf(p[j], s[j].z, acc.z);
        acc.w = fmaf(p[j], s[j].w, acc.w);
    }

    reinterpret_cast<float4*>(out)[(size_t)b * H4 * (W4 / 4) +
                                   (size_t)y * (W4 / 4) + w] = acc;
}

extern "C" void kernel_launch(void* const* d_in, const int* in_sizes, int n_in,
                              void* d_out, int out_size) {
    // Bind inputs by element count (robust to metadata ordering).
    const int CV_N = BB * CC * HH * WW;          // 262144
    const float* cv = nullptr;
    const float* sp = nullptr;
    for (int i = 0; i < n_in; i++) {
        if (in_sizes[i] == CV_N) cv = (const float*)d_in[i];
        else                     sp = (const float*)d_in[i];
    }
    float* out = (float*)d_out;

    dim3 grid(BB * H4);      // 2048 CTAs: one per (b, output row)
    dim3 block(256);         // one thread per float4 of the row
    spixel_up_kernel<<<grid, block>>>(cv, sp, out);
}

// round 11
// speedup vs baseline: 1.0494x; 1.0099x over previous
#include <cuda_runtime.h>

// spixel_upsample2d: out[b, 4h+a, 4w+d] = sum_{c<2, ky<3, kx<3}
//     cv[b, c, h+ky-1, w+kx-1] * sp[b, c*9 + ky*3+kx, 4h+a, 4w+d]
// cv: (4,2,128,256) fp32 (1 MB, L2-resident)  sp: (4,18,512,1024) fp32 (151 MB streamed)
// out: (4,1,512,1024) fp32
//
// R10: Blackwell 256-bit vector loads (ld.global.nc.v8.f32 / st.global.v8.f32).
// Thread owns 8 consecutive output floats (2 coarse cells); CTA = 2 output rows
// (same coarse row h); 3 staged batches of 6 v8 loads keep ~192B/thread in flight.

#define BB 4
#define CC 2
#define HH 128
#define WW 256
#define H4 512
#define W4 1024

__device__ __forceinline__ void ldg256(const float* __restrict__ a, float* v) {
    asm volatile("ld.global.nc.v8.f32 {%0,%1,%2,%3,%4,%5,%6,%7}, [%8];"
                 : "=f"(v[0]), "=f"(v[1]), "=f"(v[2]), "=f"(v[3]),
                   "=f"(v[4]), "=f"(v[5]), "=f"(v[6]), "=f"(v[7])
                 : "l"(a));
}

__device__ __forceinline__ void stg256(float* a, const float* v) {
    asm volatile("st.global.v8.f32 [%0], {%1,%2,%3,%4,%5,%6,%7,%8};"
                 :: "l"(a),
                    "f"(v[0]), "f"(v[1]), "f"(v[2]), "f"(v[3]),
                    "f"(v[4]), "f"(v[5]), "f"(v[6]), "f"(v[7])
                 : "memory");
}

__global__ __launch_bounds__(256, 2)
void spixel_up_kernel(const float* __restrict__ cv,
                      const float* __restrict__ sp,
                      float* __restrict__ out) {
    const int tid = threadIdx.x;
    const int r   = tid >> 7;                 // which row of the pair
    const int c8  = tid & 127;                // float8 index within row (0..127)
    const int pr  = blockIdx.x & 255;         // row-pair within batch (0..255)
    const int b   = blockIdx.x >> 8;          // batch
    const int y   = 2 * pr + r;               // output row (pair shares the quad)
    const int h   = y >> 2;                   // coarse row

    // ---- patch values for the TWO coarse cells this thread spans ----
    float p[2][18];
#pragma unroll
    for (int side = 0; side < 2; side++) {
        const int w = 2 * c8 + side;          // coarse column
#pragma unroll
        for (int c = 0; c < CC; c++) {
            const float* __restrict__ xb = cv + ((size_t)(b * CC + c) * HH) * WW;
#pragma unroll
            for (int ky = 0; ky < 3; ky++) {
                const int hh = h + ky - 1;
                const bool hv = (hh >= 0) && (hh < HH);
#pragma unroll
                for (int kx = 0; kx < 3; kx++) {
                    const int wc = w + kx - 1;
                    const bool v = hv && (wc >= 0) && (wc < WW);
                    p[side][c * 9 + ky * 3 + kx] =
                        v ? __ldg(&xb[(size_t)hh * WW + wc]) : 0.0f;
                }
            }
        }
    }

    const size_t ch_stride = (size_t)H4 * W4;          // elements per sp channel
    const float* __restrict__ spb =
        sp + ((size_t)(b * 18) * H4 + (size_t)y) * W4 + 8 * c8;

    float acc[8] = {0.f, 0.f, 0.f, 0.f, 0.f, 0.f, 0.f, 0.f};

    // ---- 3 staged batches of 6 independent 256-bit loads ----
#pragma unroll
    for (int batch = 0; batch < 3; batch++) {
        float v[6][8];
#pragma unroll
        for (int jj = 0; jj < 6; jj++)
            ldg256(spb + (size_t)(batch * 6 + jj) * ch_stride, v[jj]);
#pragma unroll
        for (int jj = 0; jj < 6; jj++) {
            const int j = batch * 6 + jj;
            const float pl = p[0][j], pr2 = p[1][j];
#pragma unroll
            for (int t = 0; t < 4; t++) {
                acc[t]     = fmaf(pl,  v[jj][t],     acc[t]);
                acc[4 + t] = fmaf(pr2, v[jj][4 + t], acc[4 + t]);
            }
        }
    }

    stg256(out + ((size_t)b * H4 + y) * W4 + 8 * c8, acc);
}

extern "C" void kernel_launch(void* const* d_in, const int* in_sizes, int n_in,
                              void* d_out, int out_size) {
    // Bind inputs by element count (robust to metadata ordering).
    const int CV_N = BB * CC * HH * WW;          // 262144
    const float* cv = nullptr;
    const float* sp = nullptr;
    for (int i = 0; i < n_in; i++) {
        if (in_sizes[i] == CV_N) cv = (const float*)d_in[i];
        else                     sp = (const float*)d_in[i];
    }
    float* out = (float*)d_out;

    dim3 grid(BB * (H4 / 2));     // 1024 CTAs: one per (batch, row pair)
    dim3 block(256);              // 2 rows x 128 float8 lanes
    spixel_up_kernel<<<grid, block>>>(cv, sp, out);
}